// round 13
// baseline (speedup 1.0000x reference)
#include <cuda_runtime.h>
#include <math.h>

#define T_DIM 4
#define C_DIM 13
#define H_DIM 361
#define W_DIM 720
#define HW    (H_DIM * W_DIM)        /* 259920  */
#define CHW   (C_DIM * HW)           /* 3378960 */
#define N2    (T_DIM * HW)           /* 1039680 */
#define W4    (W_DIM / 4)            /* 180     */
#define N4    (T_DIM * H_DIM * W4)   /* 259920  */

#define NBLK_RES (T_DIM * H_DIM)     /* 1444 blocks: one (t,h) row each */
#define ROWS_PER_SRC 10              /* U, V(3), L(3), Lt-, Lt+, sp */
#define NROWS    (2 * ROWS_PER_SRC)  /* 20 rows of 720 floats */
#define SMEM_BYTES (NROWS * W_DIM * 4)  /* 57600 -> 3 blocks/SM */

// Scratch (static device globals: allowed; no runtime allocation)
__device__ float  g_Up[N2];
__device__ float  g_Vp[N2];
__device__ float  g_Ut[N2];
__device__ float  g_Vt[N2];
__device__ float  g_lsp[N2];
__device__ float  g_lst[N2];
__device__ float  g_inv_adx[H_DIM];
__device__ float  g_consts[3];          // inv_dt, inv_2dt, inv_ady
__device__ double g_acc;
__device__ unsigned int g_bcount = 0;   // self-resetting via atomicInc wrap

__device__ __forceinline__ float4 LD4(const float* p) {
    return __ldg((const float4*)p);
}
__device__ __forceinline__ unsigned long long pol_evict_first() {
    unsigned long long pol;
    asm("createpolicy.fractional.L2::evict_first.b64 %0, 1.0;" : "=l"(pol));
    return pol;
}
// Streaming read (evict-first): keep the 216MB u/v stream from polluting L2.
__device__ __forceinline__ float4 LD4_STREAM(const float* p, unsigned long long pol) {
    float4 v;
    asm volatile("ld.global.nc.L2::cache_hint.v4.f32 {%0,%1,%2,%3}, [%4], %5;"
                 : "=f"(v.x), "=f"(v.y), "=f"(v.z), "=f"(v.w)
                 : "l"(p), "l"(pol));
    return v;
}
__device__ __forceinline__ unsigned smem_u32(const void* p) {
    return (unsigned)__cvta_generic_to_shared(p);
}
__device__ __forceinline__ void cp_async16(unsigned dst, const void* src) {
    asm volatile("cp.async.cg.shared.global [%0], [%1], 16;"
                 :: "r"(dst), "l"(src));
}

// ---------------------------------------------------------------------------
// Kernel A (unchanged champion): blockIdx.y selects work:
//   y = 0..3 : channel-weighted reduction of one tensor (13 float4 loads/thr)
//   y = 4    : log(sp) for both sources
// ---------------------------------------------------------------------------
__global__ void __launch_bounds__(256) reduce_k(
    const float* __restrict__ up, const float* __restrict__ vp,
    const float* __restrict__ ut, const float* __restrict__ vt,
    const float* __restrict__ spp, const float* __restrict__ spt,
    const float* __restrict__ lat, const float* __restrict__ lev,
    const float* __restrict__ dxp, const float* __restrict__ dtp,
    const float* __restrict__ dyp)
{
    const int ten = blockIdx.y;

    if (blockIdx.x == 0 && ten == 0) {
        for (int r = threadIdx.x; r < H_DIM; r += 256) {
            // Replicate JAX f32 sequence; accurate cos (pole rows dominate)
            float ang = (lat[r] * (float)M_PI) / 180.0f;
            float cv  = (float)cos((double)ang);
            float mpl = (float)(M_PI * 6371000.0 / 180.0);
            float adx = dxp[0] * (mpl * cv);
            g_inv_adx[r] = (float)(1.0 / (double)adx);
        }
        if (threadIdx.x == 0) {
            float dtv = dtp[0];
            float mpl = (float)(M_PI * 6371000.0 / 180.0);
            float ady = dyp[0] * mpl;
            g_consts[0] = (float)(1.0 / (double)dtv);
            g_consts[1] = (float)(1.0 / (2.0 * (double)dtv));
            g_consts[2] = (float)(1.0 / (double)ady);
            g_acc = 0.0;
        }
    }

    int i = blockIdx.x * 256 + threadIdx.x;
    if (i >= N4) return;
    int w4 = i % W4;
    int hh = (i / W4) % H_DIM;
    int t  = i / (W4 * H_DIM);
    int base2 = t * HW  + hh * W_DIM + 4 * w4;

    if (ten == 4) {
        float4 s = LD4(spp + base2);
        float4 l;
        l.x = logf(s.x); l.y = logf(s.y); l.z = logf(s.z); l.w = logf(s.w);
        *(float4*)(g_lsp + base2) = l;
        s = LD4(spt + base2);
        l.x = logf(s.x); l.y = logf(s.y); l.z = logf(s.z); l.w = logf(s.w);
        *(float4*)(g_lst + base2) = l;
        return;
    }

    const float* __restrict__ src;
    float* dst;
    switch (ten) {
        case 0: src = up; dst = g_Up; break;
        case 1: src = vp; dst = g_Vp; break;
        case 2: src = ut; dst = g_Ut; break;
        default: src = vt; dst = g_Vt; break;
    }

    float dpl[C_DIM];
    {
        dpl[0] = (__ldg(lev + 1) - __ldg(lev + 0)) * 100.0f;
        #pragma unroll
        for (int c = 1; c < C_DIM - 1; ++c)
            dpl[c] = (__ldg(lev + c + 1) - __ldg(lev + c - 1)) * 50.0f;
        dpl[C_DIM-1] = (__ldg(lev + C_DIM - 1) - __ldg(lev + C_DIM - 2)) * 100.0f;
    }

    unsigned long long pFirst = pol_evict_first();
    int base5 = t * CHW + hh * W_DIM + 4 * w4;
    float4 acc = make_float4(0.f, 0.f, 0.f, 0.f);
    #pragma unroll
    for (int c = 0; c < C_DIM; ++c) {
        float4 a = LD4_STREAM(src + base5 + c * HW, pFirst);  // evict-first
        float dp = dpl[c];
        acc.x = fmaf(dp, a.x, acc.x);
        acc.y = fmaf(dp, a.y, acc.y);
        acc.z = fmaf(dp, a.z, acc.z);
        acc.w = fmaf(dp, a.w, acc.w);
    }
    *(float4*)(dst + base2) = acc;
}

// ---------------------------------------------------------------------------
// Residual from staged smem rows (vectorized float4 LDS).
// ---------------------------------------------------------------------------
__device__ __forceinline__ float4 residual_sm(
    const float* __restrict__ b, int w4, int w, bool wlo, bool whi,
    float tscale, float hscale, float inv_adx, float inv_ady)
{
    float4 u  = ((const float4*)(b + 0 * W_DIM))[w4];
    float4 vm = ((const float4*)(b + 1 * W_DIM))[w4];
    float4 vc = ((const float4*)(b + 2 * W_DIM))[w4];
    float4 vp = ((const float4*)(b + 3 * W_DIM))[w4];
    float4 lm = ((const float4*)(b + 4 * W_DIM))[w4];
    float4 lc = ((const float4*)(b + 5 * W_DIM))[w4];
    float4 lp = ((const float4*)(b + 6 * W_DIM))[w4];
    float4 tmv= ((const float4*)(b + 7 * W_DIM))[w4];
    float4 tpv= ((const float4*)(b + 8 * W_DIM))[w4];
    float4 sp4= ((const float4*)(b + 9 * W_DIM))[w4];
    float ul = wlo ? 0.0f : b[0 * W_DIM + w - 1];
    float ur = whi ? 0.0f : b[0 * W_DIM + w + 4];
    float ll = wlo ? 0.0f : b[5 * W_DIM + w - 1];
    float lr = whi ? 0.0f : b[5 * W_DIM + w + 4];

    float4 rt4;
    rt4.x = (tpv.x - tmv.x) * tscale; rt4.y = (tpv.y - tmv.y) * tscale;
    rt4.z = (tpv.z - tmv.z) * tscale; rt4.w = (tpv.w - tmv.w) * tscale;

    float4 dlsx, dudx;
    dlsx.x = wlo ? (lc.y - lc.x) : (lc.y - ll) * 0.5f;
    dlsx.y = (lc.z - lc.x) * 0.5f;
    dlsx.z = (lc.w - lc.y) * 0.5f;
    dlsx.w = whi ? (lc.w - lc.z) : (lr - lc.z) * 0.5f;
    dudx.x = wlo ? (u.y - u.x) : (u.y - ul) * 0.5f;
    dudx.y = (u.z - u.x) * 0.5f;
    dudx.z = (u.w - u.y) * 0.5f;
    dudx.w = whi ? (u.w - u.z) : (ur - u.z) * 0.5f;

    float4 dlsy, dvdy;
    dlsy.x = (lp.x - lm.x) * hscale; dlsy.y = (lp.y - lm.y) * hscale;
    dlsy.z = (lp.z - lm.z) * hscale; dlsy.w = (lp.w - lm.w) * hscale;
    dvdy.x = (vp.x - vm.x) * hscale; dvdy.y = (vp.y - vm.y) * hscale;
    dvdy.z = (vp.z - vm.z) * hscale; dvdy.w = (vp.w - vm.w) * hscale;

    float4 rr;
    float ix = fmaf(u.x, dlsx.x, dudx.x) * inv_adx
             + fmaf(vc.x, dlsy.x, dvdy.x) * inv_ady;
    rr.x = rt4.x + __fdividef(ix, sp4.x);
    float iy = fmaf(u.y, dlsx.y, dudx.y) * inv_adx
             + fmaf(vc.y, dlsy.y, dvdy.y) * inv_ady;
    rr.y = rt4.y + __fdividef(iy, sp4.y);
    float iz = fmaf(u.z, dlsx.z, dudx.z) * inv_adx
             + fmaf(vc.z, dlsy.z, dvdy.z) * inv_ady;
    rr.z = rt4.z + __fdividef(iz, sp4.z);
    float iw = fmaf(u.w, dlsx.w, dudx.w) * inv_adx
             + fmaf(vc.w, dlsy.w, dvdy.w) * inv_ady;
    rr.w = rt4.w + __fdividef(iw, sp4.w);
    return rr;
}

// ---------------------------------------------------------------------------
// Kernel B: smem-staged stencil, one (t, h) row per block. 20 contiguous rows
// staged via cp.async (register-free MLP), compute fully vectorized from smem.
// Clamp+scale boundary scheme (validated exact in R12). 57.6KB -> 3 blocks/SM.
// ---------------------------------------------------------------------------
__global__ void __launch_bounds__(256) stencil_k(
    const float* __restrict__ spp, const float* __restrict__ spt,
    float* __restrict__ out)
{
    extern __shared__ float sm[];
    __shared__ const float* rowsrc[NROWS];

    const int tid = threadIdx.x;
    const int t   = blockIdx.x / H_DIM;
    const int h   = blockIdx.x % H_DIM;

    if (tid < NROWS) {
        int s = tid / ROWS_PER_SRC;             // 0 = pred, 1 = target
        int j = tid % ROWS_PER_SRC;
        const float* U  = s ? g_Ut  : g_Up;
        const float* V  = s ? g_Vt  : g_Vp;
        const float* L  = s ? g_lst : g_lsp;
        const float* SP = s ? spt   : spp;
        int tm = (t > 0)         ? t - 1 : t;
        int tp = (t < T_DIM - 1) ? t + 1 : t;
        const float* p;
        int r = h;
        if (j == 0)      { p = U  + t  * HW; }
        else if (j <= 3) { p = V  + t  * HW; r = h - 1 + (j - 1); }
        else if (j <= 6) { p = L  + t  * HW; r = h - 1 + (j - 4); }
        else if (j == 7) { p = L  + tm * HW; }
        else if (j == 8) { p = L  + tp * HW; }
        else             { p = SP + t  * HW; }
        if (r < 0) r = 0;
        if (r > H_DIM - 1) r = H_DIM - 1;
        rowsrc[tid] = p + r * W_DIM;
    }
    __syncthreads();

    unsigned smbase = smem_u32(sm);
    for (int idx = tid; idx < NROWS * W4; idx += 256) {
        int r  = idx / W4;
        int c4 = idx - r * W4;
        cp_async16(smbase + (unsigned)(r * W_DIM + c4 * 4) * 4u,
                   rowsrc[r] + c4 * 4);
    }
    asm volatile("cp.async.commit_group;");
    asm volatile("cp.async.wait_group 0;" ::: "memory");
    __syncthreads();

    const float inv_dt  = g_consts[0];
    const float inv_2dt = g_consts[1];
    const float inv_ady = g_consts[2];
    const float tscale  = (t == 0 || t == T_DIM - 1) ? inv_dt : inv_2dt;
    const float hscale  = (h == 0 || h == H_DIM - 1) ? 1.0f : 0.5f;
    const float inv_adx = g_inv_adx[h];

    float val = 0.0f;
    if (tid < W4) {
        const int w = 4 * tid;
        const bool wlo = (tid == 0), whi = (tid == W4 - 1);
        float4 rp = residual_sm(sm, tid, w, wlo, whi,
                                tscale, hscale, inv_adx, inv_ady);
        float4 rt = residual_sm(sm + ROWS_PER_SRC * W_DIM, tid, w, wlo, whi,
                                tscale, hscale, inv_adx, inv_ady);
        float d0 = rp.x - rt.x, d1 = rp.y - rt.y;
        float d2 = rp.z - rt.z, d3 = rp.w - rt.w;
        val = d0*d0 + d1*d1 + d2*d2 + d3*d3;
    }

    #pragma unroll
    for (int o = 16; o > 0; o >>= 1)
        val += __shfl_down_sync(0xffffffffu, val, o);

    __shared__ float sw[8];
    __shared__ bool  isLast;
    int lane = tid & 31;
    int wid  = tid >> 5;
    if (lane == 0) sw[wid] = val;
    __syncthreads();
    if (wid == 0) {
        float v = (lane < 8) ? sw[lane] : 0.0f;
        #pragma unroll
        for (int o = 4; o > 0; o >>= 1)
            v += __shfl_down_sync(0xffffffffu, v, o);
        if (lane == 0) {
            atomicAdd(&g_acc, (double)v);
            __threadfence();
            unsigned done = atomicInc(&g_bcount, NBLK_RES - 1);
            isLast = (done == NBLK_RES - 1);   // wraps to 0 -> replay-safe
        }
    }
    __syncthreads();
    if (isLast && tid == 0) {
        out[0] = (float)(g_acc / (double)N2);
    }
}

// ---------------------------------------------------------------------------
extern "C" void kernel_launch(void* const* d_in, const int* in_sizes, int n_in,
                              void* d_out, int out_size)
{
    const float* pu  = (const float*)d_in[0];
    const float* pv  = (const float*)d_in[1];
    const float* psp = (const float*)d_in[2];
    const float* tu  = (const float*)d_in[3];
    const float* tv  = (const float*)d_in[4];
    const float* tsp = (const float*)d_in[5];
    const float* lat = (const float*)d_in[6];
    const float* lev = (const float*)d_in[7];
    const float* dt  = (const float*)d_in[8];
    const float* dx  = (const float*)d_in[9];
    const float* dy  = (const float*)d_in[10];

    cudaFuncSetAttribute(stencil_k,
                         cudaFuncAttributeMaxDynamicSharedMemorySize,
                         SMEM_BYTES);

    dim3 gridA(((N4 + 255) / 256), 5);
    reduce_k<<<gridA, 256>>>(pu, pv, tu, tv, psp, tsp, lat, lev, dx, dt, dy);
    stencil_k<<<NBLK_RES, 256, SMEM_BYTES>>>(psp, tsp, (float*)d_out);
}

// round 14
// speedup vs baseline: 1.2681x; 1.2681x over previous
#include <cuda_runtime.h>
#include <math.h>

#define T_DIM 4
#define C_DIM 13
#define H_DIM 361
#define W_DIM 720
#define HW    (H_DIM * W_DIM)        /* 259920  */
#define CHW   (C_DIM * HW)           /* 3378960 */
#define N2    (T_DIM * HW)           /* 1039680 */
#define W4    (W_DIM / 4)            /* 180     */
#define N4    (T_DIM * H_DIM * W4)   /* 259920  */
#define NBLK_R ((N4 + 255) / 256)    /* 1016    */

// Scratch (static device globals: allowed; no runtime allocation)
__device__ float  g_Up[N2];
__device__ float  g_Vp[N2];
__device__ float  g_Ut[N2];
__device__ float  g_Vt[N2];
__device__ float  g_lsp[N2];
__device__ float  g_lst[N2];
__device__ float  g_inv_adx[H_DIM];
__device__ float  g_consts[3];          // inv_dt, inv_2dt, inv_ady
__device__ double g_acc;
__device__ unsigned int g_bcount = 0;   // self-resetting via atomicInc wrap

__device__ __forceinline__ float4 LD4(const float* p) {
    return __ldg((const float4*)p);
}
__device__ __forceinline__ unsigned long long pol_evict_first() {
    unsigned long long pol;
    asm("createpolicy.fractional.L2::evict_first.b64 %0, 1.0;" : "=l"(pol));
    return pol;
}
// Streaming read (evict-first): keep the 216MB u/v stream from polluting L2.
__device__ __forceinline__ float4 LD4_STREAM(const float* p, unsigned long long pol) {
    float4 v;
    asm volatile("ld.global.nc.L2::cache_hint.v4.f32 {%0,%1,%2,%3}, [%4], %5;"
                 : "=f"(v.x), "=f"(v.y), "=f"(v.z), "=f"(v.w)
                 : "l"(p), "l"(pol));
    return v;
}

// ---------------------------------------------------------------------------
// Kernel A (unchanged champion): blockIdx.y selects work:
//   y = 0..3 : channel-weighted reduction of one tensor (13 float4 loads/thr)
//   y = 4    : log(sp) for both sources
// ---------------------------------------------------------------------------
__global__ void __launch_bounds__(256) reduce_k(
    const float* __restrict__ up, const float* __restrict__ vp,
    const float* __restrict__ ut, const float* __restrict__ vt,
    const float* __restrict__ spp, const float* __restrict__ spt,
    const float* __restrict__ lat, const float* __restrict__ lev,
    const float* __restrict__ dxp, const float* __restrict__ dtp,
    const float* __restrict__ dyp)
{
    const int ten = blockIdx.y;

    if (blockIdx.x == 0 && ten == 0) {
        for (int r = threadIdx.x; r < H_DIM; r += 256) {
            // Replicate JAX f32 sequence; accurate cos (pole rows dominate)
            float ang = (lat[r] * (float)M_PI) / 180.0f;
            float cv  = (float)cos((double)ang);
            float mpl = (float)(M_PI * 6371000.0 / 180.0);
            float adx = dxp[0] * (mpl * cv);
            g_inv_adx[r] = (float)(1.0 / (double)adx);
        }
        if (threadIdx.x == 0) {
            float dtv = dtp[0];
            float mpl = (float)(M_PI * 6371000.0 / 180.0);
            float ady = dyp[0] * mpl;
            g_consts[0] = (float)(1.0 / (double)dtv);
            g_consts[1] = (float)(1.0 / (2.0 * (double)dtv));
            g_consts[2] = (float)(1.0 / (double)ady);
            g_acc = 0.0;
        }
    }

    int i = blockIdx.x * 256 + threadIdx.x;
    if (i >= N4) return;
    int w4 = i % W4;
    int hh = (i / W4) % H_DIM;
    int t  = i / (W4 * H_DIM);
    int base2 = t * HW  + hh * W_DIM + 4 * w4;

    if (ten == 4) {
        float4 s = LD4(spp + base2);
        float4 l;
        l.x = logf(s.x); l.y = logf(s.y); l.z = logf(s.z); l.w = logf(s.w);
        *(float4*)(g_lsp + base2) = l;
        s = LD4(spt + base2);
        l.x = logf(s.x); l.y = logf(s.y); l.z = logf(s.z); l.w = logf(s.w);
        *(float4*)(g_lst + base2) = l;
        return;
    }

    const float* __restrict__ src;
    float* dst;
    switch (ten) {
        case 0: src = up; dst = g_Up; break;
        case 1: src = vp; dst = g_Vp; break;
        case 2: src = ut; dst = g_Ut; break;
        default: src = vt; dst = g_Vt; break;
    }

    float dpl[C_DIM];
    {
        dpl[0] = (__ldg(lev + 1) - __ldg(lev + 0)) * 100.0f;
        #pragma unroll
        for (int c = 1; c < C_DIM - 1; ++c)
            dpl[c] = (__ldg(lev + c + 1) - __ldg(lev + c - 1)) * 50.0f;
        dpl[C_DIM-1] = (__ldg(lev + C_DIM - 1) - __ldg(lev + C_DIM - 2)) * 100.0f;
    }

    unsigned long long pFirst = pol_evict_first();
    int base5 = t * CHW + hh * W_DIM + 4 * w4;
    float4 acc = make_float4(0.f, 0.f, 0.f, 0.f);
    #pragma unroll
    for (int c = 0; c < C_DIM; ++c) {
        float4 a = LD4_STREAM(src + base5 + c * HW, pFirst);  // evict-first
        float dp = dpl[c];
        acc.x = fmaf(dp, a.x, acc.x);
        acc.y = fmaf(dp, a.y, acc.y);
        acc.z = fmaf(dp, a.z, acc.z);
        acc.w = fmaf(dp, a.w, acc.w);
    }
    *(float4*)(dst + base2) = acc;
}

// ---------------------------------------------------------------------------
// Kernel B: champion residual body, but the 8 w-neighbor scalar loads are
// replaced by warp shuffles (neighbor lane already holds the value in its
// center vector). Fallback loads only at warp edges / row wraps (predicated).
// All threads run with a clamped index so warps stay converged for shfl.
// ---------------------------------------------------------------------------
__device__ __forceinline__ float4 residual4(
    const float* __restrict__ ls, const float* __restrict__ Uf,
    const float* __restrict__ Vf, const float* __restrict__ sp,
    int base, int t, int hh, bool wlo, bool whi, bool okL, bool okR,
    float inv_dt, float inv_2dt, float inv_ady, float inv_adx)
{
    float4 c = LD4(ls + base);
    float4 u = LD4(Uf + base);

    // w-neighbor scalars via warp shuffle (lane-1 holds w-1 = its c.w;
    // lane+1 holds w+4 = its c.x). okL/okR say the shuffled value is usable.
    float ll_s = __shfl_up_sync(0xffffffffu, c.w, 1);
    float lr_s = __shfl_down_sync(0xffffffffu, c.x, 1);
    float ul_s = __shfl_up_sync(0xffffffffu, u.w, 1);
    float ur_s = __shfl_down_sync(0xffffffffu, u.x, 1);
    float lsl = wlo ? 0.0f : (okL ? ll_s : __ldg(ls + base - 1));
    float lsr = whi ? 0.0f : (okR ? lr_s : __ldg(ls + base + 4));
    float ul  = wlo ? 0.0f : (okL ? ul_s : __ldg(Uf + base - 1));
    float ur  = whi ? 0.0f : (okR ? ur_s : __ldg(Uf + base + 4));

    float4 r;
    if (t == 0) {
        float4 n = LD4(ls + base + HW);
        r.x = (n.x - c.x) * inv_dt; r.y = (n.y - c.y) * inv_dt;
        r.z = (n.z - c.z) * inv_dt; r.w = (n.w - c.w) * inv_dt;
    } else if (t == T_DIM - 1) {
        float4 p = LD4(ls + base - HW);
        r.x = (c.x - p.x) * inv_dt; r.y = (c.y - p.y) * inv_dt;
        r.z = (c.z - p.z) * inv_dt; r.w = (c.w - p.w) * inv_dt;
    } else {
        float4 n = LD4(ls + base + HW);
        float4 p = LD4(ls + base - HW);
        r.x = (n.x - p.x) * inv_2dt; r.y = (n.y - p.y) * inv_2dt;
        r.z = (n.z - p.z) * inv_2dt; r.w = (n.w - p.w) * inv_2dt;
    }

    float4 dlsx;
    dlsx.x = wlo ? (c.y - c.x) : (c.y - lsl) * 0.5f;
    dlsx.y = (c.z - c.x) * 0.5f;
    dlsx.z = (c.w - c.y) * 0.5f;
    dlsx.w = whi ? (c.w - c.z) : (lsr - c.z) * 0.5f;

    float4 dudx;
    dudx.x = wlo ? (u.y - u.x) : (u.y - ul) * 0.5f;
    dudx.y = (u.z - u.x) * 0.5f;
    dudx.z = (u.w - u.y) * 0.5f;
    dudx.w = whi ? (u.w - u.z) : (ur - u.z) * 0.5f;

    float4 v = LD4(Vf + base);
    float4 dlsy, dvdy;
    if (hh == 0) {
        float4 ld = LD4(ls + base + W_DIM);
        float4 vd = LD4(Vf + base + W_DIM);
        dlsy.x = ld.x - c.x; dlsy.y = ld.y - c.y; dlsy.z = ld.z - c.z; dlsy.w = ld.w - c.w;
        dvdy.x = vd.x - v.x; dvdy.y = vd.y - v.y; dvdy.z = vd.z - v.z; dvdy.w = vd.w - v.w;
    } else if (hh == H_DIM - 1) {
        float4 lu = LD4(ls + base - W_DIM);
        float4 vu = LD4(Vf + base - W_DIM);
        dlsy.x = c.x - lu.x; dlsy.y = c.y - lu.y; dlsy.z = c.z - lu.z; dlsy.w = c.w - lu.w;
        dvdy.x = v.x - vu.x; dvdy.y = v.y - vu.y; dvdy.z = v.z - vu.z; dvdy.w = v.w - vu.w;
    } else {
        float4 ld = LD4(ls + base + W_DIM);
        float4 lu = LD4(ls + base - W_DIM);
        float4 vd = LD4(Vf + base + W_DIM);
        float4 vu = LD4(Vf + base - W_DIM);
        dlsy.x = (ld.x - lu.x) * 0.5f; dlsy.y = (ld.y - lu.y) * 0.5f;
        dlsy.z = (ld.z - lu.z) * 0.5f; dlsy.w = (ld.w - lu.w) * 0.5f;
        dvdy.x = (vd.x - vu.x) * 0.5f; dvdy.y = (vd.y - vu.y) * 0.5f;
        dvdy.z = (vd.z - vu.z) * 0.5f; dvdy.w = (vd.w - vu.w) * 0.5f;
    }

    float4 s = LD4(sp + base);
    float4 out;
    float ix = fmaf(u.x, dlsx.x, dudx.x) * inv_adx
             + fmaf(v.x, dlsy.x, dvdy.x) * inv_ady;
    out.x = r.x + __fdividef(ix, s.x);
    float iy = fmaf(u.y, dlsx.y, dudx.y) * inv_adx
             + fmaf(v.y, dlsy.y, dvdy.y) * inv_ady;
    out.y = r.y + __fdividef(iy, s.y);
    float iz = fmaf(u.z, dlsx.z, dudx.z) * inv_adx
             + fmaf(v.z, dlsy.z, dvdy.z) * inv_ady;
    out.z = r.z + __fdividef(iz, s.z);
    float iw = fmaf(u.w, dlsx.w, dudx.w) * inv_adx
             + fmaf(v.w, dlsy.w, dvdy.w) * inv_ady;
    out.w = r.w + __fdividef(iw, s.w);
    return out;
}

__global__ void __launch_bounds__(256) residual_k(
    const float* __restrict__ spp, const float* __restrict__ spt,
    float* __restrict__ out)
{
    int i4r = blockIdx.x * 256 + threadIdx.x;
    bool active = (i4r < N4);
    int i4 = active ? i4r : (N4 - 1);       // clamp: keep warps converged

    int w4 = i4 % W4;
    int hh = (i4 / W4) % H_DIM;
    int t  = i4 / (W4 * H_DIM);
    int base = t * HW + hh * W_DIM + 4 * w4;
    bool wlo = (w4 == 0), whi = (w4 == W4 - 1);

    int lane = threadIdx.x & 31;
    // Shuffled neighbor is valid if the adjacent lane exists, is active, and
    // holds the adjacent w4 in the SAME row (no row wrap between lanes).
    bool okL = (lane > 0)  && !wlo;
    bool okR = (lane < 31) && !whi && (i4r + 1 < N4);

    float inv_dt  = g_consts[0];
    float inv_2dt = g_consts[1];
    float inv_ady = g_consts[2];
    float inv_adx = g_inv_adx[hh];

    float4 rp = residual4(g_lsp, g_Up, g_Vp, spp, base, t, hh, wlo, whi,
                          okL, okR, inv_dt, inv_2dt, inv_ady, inv_adx);
    float4 rt = residual4(g_lst, g_Ut, g_Vt, spt, base, t, hh, wlo, whi,
                          okL, okR, inv_dt, inv_2dt, inv_ady, inv_adx);
    float dx0 = rp.x - rt.x, dy0 = rp.y - rt.y;
    float dz0 = rp.z - rt.z, dw0 = rp.w - rt.w;
    float val = active ? (dx0*dx0 + dy0*dy0 + dz0*dz0 + dw0*dw0) : 0.0f;

    #pragma unroll
    for (int o = 16; o > 0; o >>= 1)
        val += __shfl_down_sync(0xffffffffu, val, o);

    __shared__ float sw[8];
    __shared__ bool  isLast;
    int wid = threadIdx.x >> 5;
    if (lane == 0) sw[wid] = val;
    __syncthreads();
    if (wid == 0) {
        float v = (lane < 8) ? sw[lane] : 0.0f;
        #pragma unroll
        for (int o = 4; o > 0; o >>= 1)
            v += __shfl_down_sync(0xffffffffu, v, o);
        if (lane == 0) {
            atomicAdd(&g_acc, (double)v);
            __threadfence();
            unsigned done = atomicInc(&g_bcount, NBLK_R - 1);
            isLast = (done == NBLK_R - 1);   // wraps to 0 -> replay-safe
        }
    }
    __syncthreads();
    if (isLast && threadIdx.x == 0) {
        out[0] = (float)(g_acc / (double)N2);
    }
}

// ---------------------------------------------------------------------------
extern "C" void kernel_launch(void* const* d_in, const int* in_sizes, int n_in,
                              void* d_out, int out_size)
{
    const float* pu  = (const float*)d_in[0];
    const float* pv  = (const float*)d_in[1];
    const float* psp = (const float*)d_in[2];
    const float* tu  = (const float*)d_in[3];
    const float* tv  = (const float*)d_in[4];
    const float* tsp = (const float*)d_in[5];
    const float* lat = (const float*)d_in[6];
    const float* lev = (const float*)d_in[7];
    const float* dt  = (const float*)d_in[8];
    const float* dx  = (const float*)d_in[9];
    const float* dy  = (const float*)d_in[10];

    dim3 gridA(NBLK_R, 5);
    reduce_k<<<gridA, 256>>>(pu, pv, tu, tv, psp, tsp, lat, lev, dx, dt, dy);
    residual_k<<<NBLK_R, 256>>>(psp, tsp, (float*)d_out);
}